// round 9
// baseline (speedup 1.0000x reference)
#include <cuda_runtime.h>
#include <cuda_bf16.h>
#include <math.h>
#include <stdint.h>

#define Bsz 64
#define Lsz 512
#define Esz 512
#define Hsz 1024
#define NG  4096     // gate-interleaved cols: col = h*4+g (0=f,1=i,2=o,3=u)
#define NCTA 128     // persistent CTAs, one 32-col group each

// smem layout (floats): gbA[64][36] @0, gbB @2304, xgA slots 0..2 @4608+s*2304,
// xgB slots @4608+6912+s*2304. Total 18432 floats = 73728 B.
#define SMEM_FLOATS 18432

// ---------------- device scratch ----------------
__device__ float g_ball[NG];
// Wh fragments: [cg 128][kk 64][img 2][lane 32][8] uint32 (bf16x2)
__device__ uint32_t g_Bfrag[(size_t)NCTA * 64 * 2 * 32 * 8];
// Wx fragments: [cg 128][kk 32][img 2][lane 32][8] (8 = 4 nt x {b0,b1})
__device__ uint32_t g_Wxfrag[(size_t)NCTA * 32 * 2 * 32 * 8];
// x fragments, time-major rows m' = t*64+b: [mt 2048][kk 32][lane 32][8]
__device__ uint32_t g_Ax[(size_t)2048 * 32 * 32 * 8];
// h pre-split bf16 hi/lo: [parity][k2 512][b 64] {hi_pair, lo_pair}
__device__ uint2 g_hsplit[2][512 * 64];
__device__ unsigned g_cnt;
__device__ volatile unsigned g_step;

// ---------------- helpers ----------------
__device__ __forceinline__ void cvt_hilo(float2 v, uint32_t& hi, uint32_t& lo) {
    asm("cvt.rn.bf16x2.f32 %0, %1, %2;" : "=r"(hi) : "f"(v.y), "f"(v.x));
    float h0 = __uint_as_float(hi << 16);
    float h1 = __uint_as_float(hi & 0xFFFF0000u);
    asm("cvt.rn.bf16x2.f32 %0, %1, %2;" : "=r"(lo) : "f"(v.y - h1), "f"(v.x - h0));
}
#define MMA16816(d, a, b0, b1)                                              \
    asm volatile(                                                           \
        "mma.sync.aligned.m16n8k16.row.col.f32.bf16.bf16.f32 "              \
        "{%0,%1,%2,%3}, {%4,%5,%6,%7}, {%8,%9}, {%0,%1,%2,%3};"             \
        : "+f"((d)[0]), "+f"((d)[1]), "+f"((d)[2]), "+f"((d)[3])            \
        : "r"((a)[0]), "r"((a)[1]), "r"((a)[2]), "r"((a)[3]),               \
          "r"(b0), "r"(b1))

// ---------------------------------------------------------------------------
// Pack: Wh fragments, Wx fragments (cg-major), bias, h0 split, counters.
// Launch 8192 x 256 (idx < 2^21).
// ---------------------------------------------------------------------------
__global__ void pack_kernel(const float* __restrict__ Wf, const float* __restrict__ Wi,
                            const float* __restrict__ Wo, const float* __restrict__ Wu,
                            const float* __restrict__ bf, const float* __restrict__ bi,
                            const float* __restrict__ bo, const float* __restrict__ bu,
                            const float* __restrict__ h0)
{
    int idx = blockIdx.x * 256 + threadIdx.x;   // 0 .. 2097151
    // ---- recurrent-weight fragments (hi/lo) ----
    {
        int r    = idx & 7;
        int lane = (idx >> 3) & 31;
        int kk   = (idx >> 8) & 63;
        int cg   = idx >> 14;
        int j = r >> 1, half = r & 1;
        int col = cg * 32 + j * 8 + (lane >> 2);
        int h = col >> 2, g = col & 3;
        int kb = kk * 16 + half * 8 + (lane & 3) * 2;
        const float* W = (g == 0) ? Wf : (g == 1) ? Wi : (g == 2) ? Wo : Wu;
        float w0 = W[(size_t)(Esz + kb) * Hsz + h];
        float w1 = W[(size_t)(Esz + kb + 1) * Hsz + h];
        uint32_t hi, lo;
        cvt_hilo(make_float2(w0, w1), hi, lo);
        size_t base = ((size_t)(cg * 64 + kk) * 2) * 256 + lane * 8 + r;
        g_Bfrag[base]       = hi;
        g_Bfrag[base + 256] = lo;
    }
    // ---- input-projection weight fragments, cg-major (hi/lo) ----
    {
        int r8   = idx & 7;                // nt*2 + b01
        int lane = (idx >> 3) & 31;
        int img  = (idx >> 8) & 1;
        int kk   = (idx >> 9) & 31;
        int cg   = idx >> 14;
        int nt = r8 >> 1, b01 = r8 & 1;
        int col = cg * 32 + nt * 8 + (lane >> 2);
        int h = col >> 2, g = col & 3;
        int k = kk * 16 + (lane & 3) * 2 + b01 * 8;
        const float* W = (g == 0) ? Wf : (g == 1) ? Wi : (g == 2) ? Wo : Wu;
        float w0 = W[(size_t)k * Hsz + h];
        float w1 = W[(size_t)(k + 1) * Hsz + h];
        uint32_t hi, lo;
        cvt_hilo(make_float2(w0, w1), hi, lo);
        g_Wxfrag[idx] = img ? lo : hi;
    }
    if (idx < NG) {
        int h = idx >> 2, g = idx & 3;
        const float* bb = (g == 0) ? bf : (g == 1) ? bi : (g == 2) ? bo : bu;
        g_ball[idx] = bb[h];
    }
    // ---- h0 split (consumed by step 0 at parity 1) ----
    if (idx < 512 * 64) {
        int k2 = idx >> 6, b = idx & 63;
        float2 v = make_float2(h0[(size_t)b * Hsz + 2 * k2],
                               h0[(size_t)b * Hsz + 2 * k2 + 1]);
        uint32_t hi, lo;
        cvt_hilo(v, hi, lo);
        g_hsplit[1][k2 * 64 + b] = make_uint2(hi, lo);
    }
    if (idx == 0) { g_cnt = 0; g_step = 0; }
}

// ---------------------------------------------------------------------------
// Split x into bf16 hi/lo fragments, time-major rows m' = t*64+b.
// Launch 65536 x 256.
// ---------------------------------------------------------------------------
__global__ void xsplit_kernel(const float* __restrict__ x)
{
    size_t idx = (size_t)blockIdx.x * 256 + threadIdx.x;   // < 16,777,216
    int r    = (int)(idx & 7);
    int lane = (int)((idx >> 3) & 31);
    int kk   = (int)((idx >> 8) & 31);
    int mt   = (int)(idx >> 13);
    int reg = r & 3, img = r >> 2;
    int rowp = mt * 16 + (lane >> 2) + (reg & 1) * 8;   // m' = t*64 + b
    int t = rowp >> 6, b = rowp & 63;
    int col = kk * 16 + (lane & 3) * 2 + (reg >> 1) * 8;
    float2 v = *(const float2*)(x + ((size_t)b * Lsz + t) * Esz + col);
    uint32_t hi, lo;
    cvt_hilo(v, hi, lo);
    g_Ax[idx] = img ? lo : hi;
}

// ---------------------------------------------------------------------------
// Fused persistent kernel: recurrence + inline input-projection slice.
// 128 CTAs x 256 thr; CTA = 32 gate-cols; 8 warps = 4 m-tiles x 2 K-halves.
// ---------------------------------------------------------------------------
__global__ __launch_bounds__(256, 1) void lstm_fused_kernel(
    const float* __restrict__ mask, const float* __restrict__ c0,
    float* __restrict__ outh, float* __restrict__ outc)
{
    extern __shared__ float sm[];

    const int tid = threadIdx.x;
    const int lane = tid & 31, wid = tid >> 5;
    const int mi = wid & 3, kh = wid >> 2;
    const int cg = blockIdx.x;

    const int pb = tid >> 2;
    const int hu = (tid & 3) * 2;
    const int k2g = cg * 4 + (tid & 3);
    float cr0 = c0[(size_t)pb * Hsz + cg * 8 + hu];
    float cr1 = c0[(size_t)pb * Hsz + cg * 8 + hu + 1];

    const int row0 = mi * 16 + (lane >> 2);
    const int kofs = (lane & 3) * 2;
    const uint32_t* bbase = g_Bfrag + ((size_t)(cg * 64 + kh * 32) * 2) * 256 + lane * 8;
    const uint32_t* wxb = g_Wxfrag + ((size_t)(cg * 32 + kh * 16) * 2) * 256 + lane * 8;
    const int kl = lane & 3;
    const int cbase = (tid & 3) * 8;
    const float4 bias0 = *(const float4*)(g_ball + cg * 32 + cbase);
    const float4 bias1 = *(const float4*)(g_ball + cg * 32 + cbase + 4);

    float* gbA = sm;
    float* gbB = sm + 2304;

    // ---- inline Xg-slice GEMM for step tt -> smem ring slot tt%3 ----
    auto compute_xg = [&](int tt) {
        int slot = tt % 3;
        float* xb = sm + 4608 + (kh ? 6912 : 0) + slot * 2304;
        const uint32_t* axp = g_Ax + ((size_t)(tt * 4 + mi) * 32 + kh * 16) * 256 + lane * 8;
        float xacc[4][4];
#pragma unroll
        for (int n = 0; n < 4; n++)
#pragma unroll
            for (int q = 0; q < 4; q++) xacc[n][q] = 0.f;
#pragma unroll 4
        for (int kkl = 0; kkl < 16; kkl++) {
            uint4 a_hi = __ldcg((const uint4*)(axp + kkl * 256));
            uint4 a_lo = __ldcg((const uint4*)(axp + kkl * 256 + 4));
            const uint32_t* bp = wxb + kkl * 512;
            uint4 q0 = *(const uint4*)bp;          // nt0,nt1 hi
            uint4 q1 = *(const uint4*)(bp + 4);    // nt2,nt3 hi
            uint4 q2 = *(const uint4*)(bp + 256);  // nt0,nt1 lo
            uint4 q3 = *(const uint4*)(bp + 260);  // nt2,nt3 lo
            uint32_t ah[4] = {a_hi.x, a_hi.y, a_hi.z, a_hi.w};
            uint32_t al[4] = {a_lo.x, a_lo.y, a_lo.z, a_lo.w};
            MMA16816(xacc[0], ah, q0.x, q0.y); MMA16816(xacc[1], ah, q0.z, q0.w);
            MMA16816(xacc[2], ah, q1.x, q1.y); MMA16816(xacc[3], ah, q1.z, q1.w);
            MMA16816(xacc[0], ah, q2.x, q2.y); MMA16816(xacc[1], ah, q2.z, q2.w);
            MMA16816(xacc[2], ah, q3.x, q3.y); MMA16816(xacc[3], ah, q3.z, q3.w);
            MMA16816(xacc[0], al, q0.x, q0.y); MMA16816(xacc[1], al, q0.z, q0.w);
            MMA16816(xacc[2], al, q1.x, q1.y); MMA16816(xacc[3], al, q1.z, q1.w);
        }
#pragma unroll
        for (int nt = 0; nt < 4; nt++) {
            int jc = nt * 8 + kofs;
            *(float2*)&xb[row0 * 36 + jc]       = make_float2(xacc[nt][0], xacc[nt][1]);
            *(float2*)&xb[(row0 + 8) * 36 + jc] = make_float2(xacc[nt][2], xacc[nt][3]);
        }
    };

    compute_xg(0);
    compute_xg(1);

    for (int t = 0; t < Lsz; t++) {
        if (t + 2 < Lsz) compute_xg(t + 2);   // fills sync-wait idle
        if (t > 0) {
            if (tid == 0) {
                while (g_step < (unsigned)t) __nanosleep(32);
            }
            __syncthreads();
        }
        const uint2* hs = g_hsplit[(t + 1) & 1];

        float acc[4][4];
#pragma unroll
        for (int j = 0; j < 4; j++)
#pragma unroll
            for (int q = 0; q < 4; q++) acc[j][q] = 0.f;

        uint2 fA[2][4];
        uint4 fB[2][4];
        auto loadA = [&](int s, int it) {
            const uint2* p = hs + (kh * 256 + it * 8 + kl) * 64 + row0;
            fA[s][0] = __ldcg(p);
            fA[s][1] = __ldcg(p + 8);
            fA[s][2] = __ldcg(p + 256);
            fA[s][3] = __ldcg(p + 264);
        };
        auto loadB = [&](int s, int it) {
            const uint32_t* bp = bbase + (size_t)it * 512;
            fB[s][0] = *(const uint4*)bp;
            fB[s][1] = *(const uint4*)(bp + 4);
            fB[s][2] = *(const uint4*)(bp + 256);
            fB[s][3] = *(const uint4*)(bp + 260);
        };
        loadA(0, 0); loadB(0, 0);
        loadA(1, 1); loadB(1, 1);

#pragma unroll 4
        for (int it = 0; it < 32; it++) {
            const int cur = it & 1;
            uint32_t ah[4], al[4];
#pragma unroll
            for (int j = 0; j < 4; j++) { ah[j] = fA[cur][j].x; al[j] = fA[cur][j].y; }
            uint4 bh0 = fB[cur][0], bh1 = fB[cur][1];
            uint4 bl0 = fB[cur][2], bl1 = fB[cur][3];
            if (it + 2 < 32) { loadA(cur, it + 2); loadB(cur, it + 2); }

            MMA16816(acc[0], ah, bh0.x, bh0.y);
            MMA16816(acc[1], ah, bh0.z, bh0.w);
            MMA16816(acc[2], ah, bh1.x, bh1.y);
            MMA16816(acc[3], ah, bh1.z, bh1.w);
            MMA16816(acc[0], ah, bl0.x, bl0.y);
            MMA16816(acc[1], ah, bl0.z, bl0.w);
            MMA16816(acc[2], ah, bl1.x, bl1.y);
            MMA16816(acc[3], ah, bl1.z, bl1.w);
            MMA16816(acc[0], al, bh0.x, bh0.y);
            MMA16816(acc[1], al, bh0.z, bh0.w);
            MMA16816(acc[2], al, bh1.x, bh1.y);
            MMA16816(acc[3], al, bh1.z, bh1.w);
        }

        {
            float* gb = (kh == 0) ? gbA : gbB;
#pragma unroll
            for (int j = 0; j < 4; j++) {
                int jc = j * 8 + kofs;
                *(float2*)&gb[row0 * 36 + jc]       = make_float2(acc[j][0], acc[j][1]);
                *(float2*)&gb[(row0 + 8) * 36 + jc] = make_float2(acc[j][2], acc[j][3]);
            }
        }
        __syncthreads();

        // fused gates / cell update; produce split h for next step
        {
            int slot = t % 3;
            const float* xA = sm + 4608 + slot * 2304 + pb * 36 + cbase;
            const float* xB = xA + 6912;
            float4 xa0 = *(const float4*)xA;
            float4 xa1 = *(const float4*)(xA + 4);
            float4 xb0 = *(const float4*)xB;
            float4 xb1 = *(const float4*)(xB + 4);
            float4 a0 = *(const float4*)&gbA[pb * 36 + cbase];
            float4 a1 = *(const float4*)&gbA[pb * 36 + cbase + 4];
            float4 b0 = *(const float4*)&gbB[pb * 36 + cbase];
            float4 b1 = *(const float4*)&gbB[pb * 36 + cbase + 4];
            float mk = mask[(size_t)pb * Lsz + t];

            float p0 = xa0.x + xb0.x + a0.x + b0.x + bias0.x;
            float p1 = xa0.y + xb0.y + a0.y + b0.y + bias0.y;
            float p2 = xa0.z + xb0.z + a0.z + b0.z + bias0.z;
            float p3 = xa0.w + xb0.w + a0.w + b0.w + bias0.w;
            float f0 = 1.f / (1.f + expf(-p0));
            float i0 = 1.f / (1.f + expf(-p1));
            float o0 = 1.f / (1.f + expf(-p2));
            float u0 = tanhf(p3);
            float nc0 = f0 * cr0 + i0 * u0;
            float nh0 = o0 * tanhf(nc0);
            nh0 *= mk; nc0 *= mk;

            float q0 = xa1.x + xb1.x + a1.x + b1.x + bias1.x;
            float q1 = xa1.y + xb1.y + a1.y + b1.y + bias1.y;
            float q2 = xa1.z + xb1.z + a1.z + b1.z + bias1.z;
            float q3 = xa1.w + xb1.w + a1.w + b1.w + bias1.w;
            float f1 = 1.f / (1.f + expf(-q0));
            float i1 = 1.f / (1.f + expf(-q1));
            float o1 = 1.f / (1.f + expf(-q2));
            float u1 = tanhf(q3);
            float nc1 = f1 * cr1 + i1 * u1;
            float nh1 = o1 * tanhf(nc1);
            nh1 *= mk; nc1 *= mk;

            cr0 = nc0; cr1 = nc1;

            size_t oi = ((size_t)pb * Lsz + t) * Hsz + cg * 8 + hu;
            *(float2*)(outh + oi) = make_float2(nh0, nh1);
            *(float2*)(outc + oi) = make_float2(nc0, nc1);

            uint32_t hi, lo;
            cvt_hilo(make_float2(nh0, nh1), hi, lo);
            g_hsplit[t & 1][k2g * 64 + pb] = make_uint2(hi, lo);
        }
        __threadfence();
        __syncthreads();
        if (tid == 0) {
            unsigned old = atomicAdd(&g_cnt, 1u);
            if (old == 128u * (unsigned)(t + 1) - 1u) g_step = (unsigned)(t + 1);
        }
    }
}

// ---------------------------------------------------------------------------
extern "C" void kernel_launch(void* const* d_in, const int* in_sizes, int n_in,
                              void* d_out, int out_size)
{
    const float* x    = (const float*)d_in[0];
    const float* mask = (const float*)d_in[1];
    const float* Wf   = (const float*)d_in[2];
    const float* bf   = (const float*)d_in[3];
    const float* Wi   = (const float*)d_in[4];
    const float* bi   = (const float*)d_in[5];
    const float* Wo   = (const float*)d_in[6];
    const float* bo   = (const float*)d_in[7];
    const float* Wu   = (const float*)d_in[8];
    const float* bu   = (const float*)d_in[9];
    const float* h0   = (const float*)d_in[10];
    const float* c0   = (const float*)d_in[11];

    float* outh = (float*)d_out;
    float* outc = outh + (size_t)Bsz * Lsz * Hsz;

    cudaFuncSetAttribute(lstm_fused_kernel,
                         cudaFuncAttributeMaxDynamicSharedMemorySize,
                         SMEM_FLOATS * 4);

    pack_kernel<<<8192, 256>>>(Wf, Wi, Wo, Wu, bf, bi, bo, bu, h0);
    xsplit_kernel<<<65536, 256>>>(x);
    lstm_fused_kernel<<<NCTA, 256, SMEM_FLOATS * 4>>>(mask, c0, outh, outc);
}

// round 10
// speedup vs baseline: 1.4510x; 1.4510x over previous
#include <cuda_runtime.h>
#include <cuda_fp16.h>
#include <math.h>
#include <stdint.h>

#define Bsz 64
#define Lsz 512
#define Esz 512
#define Hsz 1024
#define NG  4096     // gate-interleaved cols: col = h*4+g (0=f,1=i,2=o,3=u)
#define NCTA 128     // persistent CTAs, one 32-col group each

// smem (floats): gbA[64][36] @0, gbB @2304, xgA slots @4608+s*2304, xgB @+6912
#define SMEM_FLOATS 18432

// ---------------- device scratch ----------------
__device__ float g_ball[NG];
// Wh fp16 frags: [cg 128][kk 64][lane 32][8] (8 = 4 j-tiles x {b0,b1})
__device__ uint32_t g_Whf[(size_t)128 * 64 * 32 * 8];
// Wx fp16 frags: [cg 128][kk 32][lane 32][8]
__device__ uint32_t g_Wxf[(size_t)128 * 32 * 32 * 8];
// x fp16 frags, time-major rows m' = t*64+b: [mt 2048][kk 32][lane 32][4]
__device__ uint32_t g_Axf[(size_t)2048 * 32 * 32 * 4];
// h fp16 pairs: [parity][k2 512][b 64]
__device__ uint32_t g_hf[2][512 * 64];
__device__ unsigned g_cnt;
__device__ volatile unsigned g_step;

// ---------------- helpers ----------------
__device__ __forceinline__ uint32_t f16pair(float2 v) {
    uint32_t r;
    asm("cvt.rn.f16x2.f32 %0, %1, %2;" : "=r"(r) : "f"(v.y), "f"(v.x));
    return r;
}
#define MMAF16(d, a, b0, b1)                                                \
    asm volatile(                                                           \
        "mma.sync.aligned.m16n8k16.row.col.f32.f16.f16.f32 "                \
        "{%0,%1,%2,%3}, {%4,%5,%6,%7}, {%8,%9}, {%0,%1,%2,%3};"             \
        : "+f"((d)[0]), "+f"((d)[1]), "+f"((d)[2]), "+f"((d)[3])            \
        : "r"((a)[0]), "r"((a)[1]), "r"((a)[2]), "r"((a)[3]),               \
          "r"(b0), "r"(b1))

// ---------------------------------------------------------------------------
// Pack: Wh/Wx fp16 fragments, bias, h0 split, counters. 8192 x 256.
// ---------------------------------------------------------------------------
__global__ void pack_kernel(const float* __restrict__ Wf, const float* __restrict__ Wi,
                            const float* __restrict__ Wo, const float* __restrict__ Wu,
                            const float* __restrict__ bf, const float* __restrict__ bi,
                            const float* __restrict__ bo, const float* __restrict__ bu,
                            const float* __restrict__ h0)
{
    int idx = blockIdx.x * 256 + threadIdx.x;   // 0 .. 2097151
    // ---- Wh fragments: idx = ((cg*64+kk)*32+lane)*8 + r3 ----
    {
        int r3   = idx & 7;
        int lane = (idx >> 3) & 31;
        int kk   = (idx >> 8) & 63;
        int cg   = idx >> 14;
        int j = r3 >> 1, half = r3 & 1;
        int col = cg * 32 + j * 8 + (lane >> 2);
        int h = col >> 2, g = col & 3;
        int k = kk * 16 + half * 8 + (lane & 3) * 2;
        const float* W = (g == 0) ? Wf : (g == 1) ? Wi : (g == 2) ? Wo : Wu;
        float w0 = W[(size_t)(Esz + k) * Hsz + h];
        float w1 = W[(size_t)(Esz + k + 1) * Hsz + h];
        g_Whf[idx] = f16pair(make_float2(w0, w1));
    }
    // ---- Wx fragments: idx = ((cg*32+kk)*32+lane)*8 + r3 ----
    if (idx < (1 << 20)) {
        int r3   = idx & 7;
        int lane = (idx >> 3) & 31;
        int kk   = (idx >> 8) & 31;
        int cg   = idx >> 13;
        int nt = r3 >> 1, b01 = r3 & 1;
        int col = cg * 32 + nt * 8 + (lane >> 2);
        int h = col >> 2, g = col & 3;
        int k = kk * 16 + (lane & 3) * 2 + b01 * 8;
        const float* W = (g == 0) ? Wf : (g == 1) ? Wi : (g == 2) ? Wo : Wu;
        float w0 = W[(size_t)k * Hsz + h];
        float w1 = W[(size_t)(k + 1) * Hsz + h];
        g_Wxf[idx] = f16pair(make_float2(w0, w1));
    }
    if (idx < NG) {
        int h = idx >> 2, g = idx & 3;
        const float* bb = (g == 0) ? bf : (g == 1) ? bi : (g == 2) ? bo : bu;
        g_ball[idx] = bb[h];
    }
    // ---- h0 split (read by step 0 at parity 1) ----
    if (idx < 512 * 64) {
        int k2 = idx >> 6, b = idx & 63;
        g_hf[1][idx] = f16pair(make_float2(h0[(size_t)b * Hsz + 2 * k2],
                                           h0[(size_t)b * Hsz + 2 * k2 + 1]));
    }
    if (idx == 0) { g_cnt = 0; g_step = 0; }
}

// ---------------------------------------------------------------------------
// x -> fp16 fragments, time-major. 32768 x 256 (idx < 2^23).
// ---------------------------------------------------------------------------
__global__ void xsplit_kernel(const float* __restrict__ x)
{
    size_t idx = (size_t)blockIdx.x * 256 + threadIdx.x;
    int r    = (int)(idx & 3);
    int lane = (int)((idx >> 2) & 31);
    int kk   = (int)((idx >> 7) & 31);
    int mt   = (int)(idx >> 12);
    int rowp = mt * 16 + (lane >> 2) + (r & 1) * 8;    // m' = t*64 + b
    int t = rowp >> 6, b = rowp & 63;
    int col = kk * 16 + (lane & 3) * 2 + (r >> 1) * 8;
    float2 v = *(const float2*)(x + ((size_t)b * Lsz + t) * Esz + col);
    g_Axf[idx] = f16pair(v);
}

// ---------------------------------------------------------------------------
// Fused persistent kernel: recurrence + inline Xg slice, single-pass fp16.
// ---------------------------------------------------------------------------
__global__ __launch_bounds__(256, 1) void lstm_fused_kernel(
    const float* __restrict__ mask, const float* __restrict__ c0,
    float* __restrict__ outh, float* __restrict__ outc)
{
    extern __shared__ float sm[];

    const int tid = threadIdx.x;
    const int lane = tid & 31, wid = tid >> 5;
    const int mi = wid & 3, kh = wid >> 2;
    const int cg = blockIdx.x;

    const int pb = tid >> 2;
    const int hu = (tid & 3) * 2;
    const int k2g = cg * 4 + (tid & 3);
    float cr0 = c0[(size_t)pb * Hsz + cg * 8 + hu];
    float cr1 = c0[(size_t)pb * Hsz + cg * 8 + hu + 1];

    const int row0 = mi * 16 + (lane >> 2);
    const int kofs = (lane & 3) * 2;
    const int kl = lane & 3;
    const uint32_t* whb = g_Whf + ((size_t)(cg * 64 + kh * 32) * 32 + lane) * 8;
    const uint32_t* wxb = g_Wxf + ((size_t)(cg * 32 + kh * 16) * 32 + lane) * 8;
    const int cbase = (tid & 3) * 8;
    const float4 bias0 = *(const float4*)(g_ball + cg * 32 + cbase);
    const float4 bias1 = *(const float4*)(g_ball + cg * 32 + cbase + 4);

    float* gbA = sm;
    float* gbB = sm + 2304;

    // ---- inline Xg-slice GEMM for step tt -> smem ring slot tt%3 ----
    auto compute_xg = [&](int tt) {
        int slot = tt % 3;
        float* xb = sm + 4608 + (kh ? 6912 : 0) + slot * 2304;
        const uint32_t* axp = g_Axf + ((size_t)((tt * 4 + mi) * 32 + kh * 16) * 32 + lane) * 4;
        float xacc[4][4];
#pragma unroll
        for (int n = 0; n < 4; n++)
#pragma unroll
            for (int q = 0; q < 4; q++) xacc[n][q] = 0.f;

        uint4 fa[2], q0[2], q1[2];
        auto loadx = [&](int s, int k) {
            fa[s] = __ldcg((const uint4*)(axp + k * 128));
            q0[s] = *(const uint4*)(wxb + k * 256);
            q1[s] = *(const uint4*)(wxb + k * 256 + 4);
        };
        loadx(0, 0); loadx(1, 1);
#pragma unroll 4
        for (int kkl = 0; kkl < 16; kkl++) {
            const int cur = kkl & 1;
            uint32_t ua[4] = {fa[cur].x, fa[cur].y, fa[cur].z, fa[cur].w};
            uint4 b0 = q0[cur], b1 = q1[cur];
            if (kkl + 2 < 16) loadx(cur, kkl + 2);
            MMAF16(xacc[0], ua, b0.x, b0.y);
            MMAF16(xacc[1], ua, b0.z, b0.w);
            MMAF16(xacc[2], ua, b1.x, b1.y);
            MMAF16(xacc[3], ua, b1.z, b1.w);
        }
#pragma unroll
        for (int nt = 0; nt < 4; nt++) {
            int jc = nt * 8 + kofs;
            *(float2*)&xb[row0 * 36 + jc]       = make_float2(xacc[nt][0], xacc[nt][1]);
            *(float2*)&xb[(row0 + 8) * 36 + jc] = make_float2(xacc[nt][2], xacc[nt][3]);
        }
    };

    compute_xg(0);
    compute_xg(1);

    for (int t = 0; t < Lsz; t++) {
        if (t + 2 < Lsz) compute_xg(t + 2);
        if (t > 0) {
            if (tid == 0) {
                while (g_step < (unsigned)t) __nanosleep(32);
            }
            __syncthreads();
        }
        const uint32_t* hs = g_hf[(t + 1) & 1];

        float acc[4][4];
#pragma unroll
        for (int j = 0; j < 4; j++)
#pragma unroll
            for (int q = 0; q < 4; q++) acc[j][q] = 0.f;

        uint32_t fA[4][4];
        uint4 fB[4][2];
        auto loadA = [&](int s, int it) {
            const uint32_t* p = hs + (kh * 256 + it * 8 + kl) * 64 + row0;
            fA[s][0] = __ldcg(p);
            fA[s][1] = __ldcg(p + 8);
            fA[s][2] = __ldcg(p + 256);
            fA[s][3] = __ldcg(p + 264);
        };
        auto loadB = [&](int s, int it) {
            const uint32_t* bp = whb + (size_t)it * 256;
            fB[s][0] = *(const uint4*)bp;
            fB[s][1] = *(const uint4*)(bp + 4);
        };
        loadA(0, 0); loadB(0, 0);
        loadA(1, 1); loadB(1, 1);
        loadA(2, 2); loadB(2, 2);

#pragma unroll 4
        for (int it = 0; it < 32; it++) {
            const int cur = it & 3;
            uint32_t ah[4] = {fA[cur][0], fA[cur][1], fA[cur][2], fA[cur][3]};
            uint4 q0 = fB[cur][0], q1 = fB[cur][1];
            if (it + 3 < 32) {
                int nx = (it + 3) & 3;
                loadA(nx, it + 3);
                loadB(nx, it + 3);
            }
            MMAF16(acc[0], ah, q0.x, q0.y);
            MMAF16(acc[1], ah, q0.z, q0.w);
            MMAF16(acc[2], ah, q1.x, q1.y);
            MMAF16(acc[3], ah, q1.z, q1.w);
        }

        {
            float* gb = (kh == 0) ? gbA : gbB;
#pragma unroll
            for (int j = 0; j < 4; j++) {
                int jc = j * 8 + kofs;
                *(float2*)&gb[row0 * 36 + jc]       = make_float2(acc[j][0], acc[j][1]);
                *(float2*)&gb[(row0 + 8) * 36 + jc] = make_float2(acc[j][2], acc[j][3]);
            }
        }
        __syncthreads();

        // fused gates / cell update; produce fp16 h for next step
        {
            int slot = t % 3;
            const float* xA = sm + 4608 + slot * 2304 + pb * 36 + cbase;
            const float* xB = xA + 6912;
            float4 xa0 = *(const float4*)xA;
            float4 xa1 = *(const float4*)(xA + 4);
            float4 xb0 = *(const float4*)xB;
            float4 xb1 = *(const float4*)(xB + 4);
            float4 a0 = *(const float4*)&gbA[pb * 36 + cbase];
            float4 a1 = *(const float4*)&gbA[pb * 36 + cbase + 4];
            float4 b0 = *(const float4*)&gbB[pb * 36 + cbase];
            float4 b1 = *(const float4*)&gbB[pb * 36 + cbase + 4];
            float mk = mask[(size_t)pb * Lsz + t];

            float p0 = xa0.x + xb0.x + a0.x + b0.x + bias0.x;
            float p1 = xa0.y + xb0.y + a0.y + b0.y + bias0.y;
            float p2 = xa0.z + xb0.z + a0.z + b0.z + bias0.z;
            float p3 = xa0.w + xb0.w + a0.w + b0.w + bias0.w;
            float f0 = 1.f / (1.f + expf(-p0));
            float i0 = 1.f / (1.f + expf(-p1));
            float o0 = 1.f / (1.f + expf(-p2));
            float u0 = tanhf(p3);
            float nc0 = f0 * cr0 + i0 * u0;
            float nh0 = o0 * tanhf(nc0);
            nh0 *= mk; nc0 *= mk;

            float q0 = xa1.x + xb1.x + a1.x + b1.x + bias1.x;
            float q1 = xa1.y + xb1.y + a1.y + b1.y + bias1.y;
            float q2 = xa1.z + xb1.z + a1.z + b1.z + bias1.z;
            float q3 = xa1.w + xb1.w + a1.w + b1.w + bias1.w;
            float f1 = 1.f / (1.f + expf(-q0));
            float i1 = 1.f / (1.f + expf(-q1));
            float o1 = 1.f / (1.f + expf(-q2));
            float u1 = tanhf(q3);
            float nc1 = f1 * cr1 + i1 * u1;
            float nh1 = o1 * tanhf(nc1);
            nh1 *= mk; nc1 *= mk;

            cr0 = nc0; cr1 = nc1;

            size_t oi = ((size_t)pb * Lsz + t) * Hsz + cg * 8 + hu;
            *(float2*)(outh + oi) = make_float2(nh0, nh1);
            *(float2*)(outc + oi) = make_float2(nc0, nc1);

            g_hf[t & 1][k2g * 64 + pb] = f16pair(make_float2(nh0, nh1));
        }
        __threadfence();
        __syncthreads();
        if (tid == 0) {
            unsigned old = atomicAdd(&g_cnt, 1u);
            if (old == 128u * (unsigned)(t + 1) - 1u) g_step = (unsigned)(t + 1);
        }
    }
}

// ---------------------------------------------------------------------------
extern "C" void kernel_launch(void* const* d_in, const int* in_sizes, int n_in,
                              void* d_out, int out_size)
{
    const float* x    = (const float*)d_in[0];
    const float* mask = (const float*)d_in[1];
    const float* Wf   = (const float*)d_in[2];
    const float* bf   = (const float*)d_in[3];
    const float* Wi   = (const float*)d_in[4];
    const float* bi   = (const float*)d_in[5];
    const float* Wo   = (const float*)d_in[6];
    const float* bo   = (const float*)d_in[7];
    const float* Wu   = (const float*)d_in[8];
    const float* bu   = (const float*)d_in[9];
    const float* h0   = (const float*)d_in[10];
    const float* c0   = (const float*)d_in[11];

    float* outh = (float*)d_out;
    float* outc = outh + (size_t)Bsz * Lsz * Hsz;

    cudaFuncSetAttribute(lstm_fused_kernel,
                         cudaFuncAttributeMaxDynamicSharedMemorySize,
                         SMEM_FLOATS * 4);

    pack_kernel<<<8192, 256>>>(Wf, Wi, Wo, Wu, bf, bi, bo, bu, h0);
    xsplit_kernel<<<32768, 256>>>(x);
    lstm_fused_kernel<<<NCTA, 256, SMEM_FLOATS * 4>>>(mask, c0, outh, outc);
}

// round 11
// speedup vs baseline: 1.6948x; 1.1680x over previous
#include <cuda_runtime.h>
#include <cuda_fp16.h>
#include <math.h>
#include <stdint.h>

#define Bsz 64
#define Lsz 512
#define Esz 512
#define Hsz 1024
#define NG  4096     // gate-interleaved cols: col = h*4+g (0=f,1=i,2=o,3=u)
#define NCTA 128     // persistent CTAs, one 32-col group each

// smem (floats): gbA[64][36] @0, gbB @2304, xgA slots @4608+s*2304, xgB @+6912
#define SMEM_FLOATS 18432

// ---------------- device scratch ----------------
__device__ float g_ball[NG];
// Wh fp16 frags: [cg 128][kk 64][lane 32][8] (8 = 4 j-tiles x {b0,b1})
__device__ uint32_t g_Whf[(size_t)128 * 64 * 32 * 8];
// Wx fp16 frags: [cg 128][kk 32][lane 32][8]
__device__ uint32_t g_Wxf[(size_t)128 * 32 * 32 * 8];
// x fp16 frags, time-major rows m' = t*64+b: [mt 2048][kk 32][lane 32][4]
__device__ uint32_t g_Axf[(size_t)2048 * 32 * 32 * 4];
// h fp16 fragment-quads: [parity][quad 8192][4]
//   quad(kb,mi,q,klo) = ((kb*4+mi)*8+q)*4+klo ; slot r = s + 2*hi
//   covers (row = mi*16+q+8s, k2 = kb*8+klo+4hi)
__device__ uint32_t g_hf2[2][32768];
__device__ unsigned g_cnt;
__device__ volatile unsigned g_step;

// ---------------- helpers ----------------
__device__ __forceinline__ uint32_t f16pair(float2 v) {
    uint32_t r;
    asm("cvt.rn.f16x2.f32 %0, %1, %2;" : "=r"(r) : "f"(v.y), "f"(v.x));
    return r;
}
#define MMAF16(d, a, b0, b1)                                                \
    asm volatile(                                                           \
        "mma.sync.aligned.m16n8k16.row.col.f32.f16.f16.f32 "                \
        "{%0,%1,%2,%3}, {%4,%5,%6,%7}, {%8,%9}, {%0,%1,%2,%3};"             \
        : "+f"((d)[0]), "+f"((d)[1]), "+f"((d)[2]), "+f"((d)[3])            \
        : "r"((a)[0]), "r"((a)[1]), "r"((a)[2]), "r"((a)[3]),               \
          "r"(b0), "r"(b1))

// ---------------------------------------------------------------------------
// Pack: Wh/Wx fp16 fragments, bias, h0 quads, counters. 8192 x 256.
// ---------------------------------------------------------------------------
__global__ void pack_kernel(const float* __restrict__ Wf, const float* __restrict__ Wi,
                            const float* __restrict__ Wo, const float* __restrict__ Wu,
                            const float* __restrict__ bf, const float* __restrict__ bi,
                            const float* __restrict__ bo, const float* __restrict__ bu,
                            const float* __restrict__ h0)
{
    int idx = blockIdx.x * 256 + threadIdx.x;   // 0 .. 2097151
    // ---- Wh fragments: idx = ((cg*64+kk)*32+lane)*8 + r3 ----
    {
        int r3   = idx & 7;
        int lane = (idx >> 3) & 31;
        int kk   = (idx >> 8) & 63;
        int cg   = idx >> 14;
        int j = r3 >> 1, half = r3 & 1;
        int col = cg * 32 + j * 8 + (lane >> 2);
        int h = col >> 2, g = col & 3;
        int k = kk * 16 + half * 8 + (lane & 3) * 2;
        const float* W = (g == 0) ? Wf : (g == 1) ? Wi : (g == 2) ? Wo : Wu;
        float w0 = W[(size_t)(Esz + k) * Hsz + h];
        float w1 = W[(size_t)(Esz + k + 1) * Hsz + h];
        g_Whf[idx] = f16pair(make_float2(w0, w1));
    }
    // ---- Wx fragments: idx = ((cg*32+kk)*32+lane)*8 + r3 ----
    if (idx < (1 << 20)) {
        int r3   = idx & 7;
        int lane = (idx >> 3) & 31;
        int kk   = (idx >> 8) & 31;
        int cg   = idx >> 13;
        int nt = r3 >> 1, b01 = r3 & 1;
        int col = cg * 32 + nt * 8 + (lane >> 2);
        int h = col >> 2, g = col & 3;
        int k = kk * 16 + (lane & 3) * 2 + b01 * 8;
        const float* W = (g == 0) ? Wf : (g == 1) ? Wi : (g == 2) ? Wo : Wu;
        float w0 = W[(size_t)k * Hsz + h];
        float w1 = W[(size_t)(k + 1) * Hsz + h];
        g_Wxf[idx] = f16pair(make_float2(w0, w1));
    }
    if (idx < NG) {
        int h = idx >> 2, g = idx & 3;
        const float* bb = (g == 0) ? bf : (g == 1) ? bi : (g == 2) ? bo : bu;
        g_ball[idx] = bb[h];
    }
    // ---- h0 quads (read by step 0 at parity 1) ----
    if (idx < 32768) {
        int r   = idx & 3;
        int klo = (idx >> 2) & 3;
        int q   = (idx >> 4) & 7;
        int mi  = (idx >> 7) & 3;
        int kb  = idx >> 9;
        int s = r & 1, hi = r >> 1;
        int b = mi * 16 + q + 8 * s;
        int k2 = kb * 8 + klo + 4 * hi;
        g_hf2[1][idx] = f16pair(make_float2(h0[(size_t)b * Hsz + 2 * k2],
                                            h0[(size_t)b * Hsz + 2 * k2 + 1]));
    }
    if (idx == 0) { g_cnt = 0; g_step = 0; }
}

// ---------------------------------------------------------------------------
// x -> fp16 fragments, time-major. 32768 x 256 (idx < 2^23).
// ---------------------------------------------------------------------------
__global__ void xsplit_kernel(const float* __restrict__ x)
{
    size_t idx = (size_t)blockIdx.x * 256 + threadIdx.x;
    int r    = (int)(idx & 3);
    int lane = (int)((idx >> 2) & 31);
    int kk   = (int)((idx >> 7) & 31);
    int mt   = (int)(idx >> 12);
    int rowp = mt * 16 + (lane >> 2) + (r & 1) * 8;    // m' = t*64 + b
    int t = rowp >> 6, b = rowp & 63;
    int col = kk * 16 + (lane & 3) * 2 + (r >> 1) * 8;
    float2 v = *(const float2*)(x + ((size_t)b * Lsz + t) * Esz + col);
    g_Axf[idx] = f16pair(v);
}

// ---------------------------------------------------------------------------
// Fused persistent kernel: recurrence + inline Xg slice, fp16 single-pass.
// ---------------------------------------------------------------------------
__global__ __launch_bounds__(256, 1) void lstm_fused_kernel(
    const float* __restrict__ mask, const float* __restrict__ c0,
    float* __restrict__ outh, float* __restrict__ outc)
{
    extern __shared__ float sm[];

    const int tid = threadIdx.x;
    const int lane = tid & 31, wid = tid >> 5;
    const int mi = wid & 3, kh = wid >> 2;
    const int cg = blockIdx.x;

    const int pb = tid >> 2;
    const int hu = (tid & 3) * 2;
    const int k2g = cg * 4 + (tid & 3);
    float cr0 = c0[(size_t)pb * Hsz + cg * 8 + hu];
    float cr1 = c0[(size_t)pb * Hsz + cg * 8 + hu + 1];

    const int row0 = mi * 16 + (lane >> 2);
    const int kofs = (lane & 3) * 2;
    const uint32_t* whb = g_Whf + ((size_t)(cg * 64 + kh * 32) * 32 + lane) * 8;
    const uint32_t* wxb = g_Wxf + ((size_t)(cg * 32 + kh * 16) * 32 + lane) * 8;
    const int cbase = (tid & 3) * 8;
    const float4 bias0 = *(const float4*)(g_ball + cg * 32 + cbase);
    const float4 bias1 = *(const float4*)(g_ball + cg * 32 + cbase + 4);

    // writer slot in fragment-quad layout
    const int kb_w = k2g >> 3, klo_w = k2g & 3, hi_w = (k2g >> 2) & 1;
    const int mi_w = pb >> 4, q_w = pb & 7, s_w = (pb >> 3) & 1;
    const size_t widx = ((size_t)((kb_w * 4 + mi_w) * 8 + q_w) * 4 + klo_w) * 4
                        + (s_w + 2 * hi_w);

    // reader base offset (uint32) at it=0: quad (kb=kh*32, mi), lane
    const size_t hroff = ((size_t)((kh * 32 * 4 + mi)) * 32 + lane) * 4;

    float* gbA = sm;
    float* gbB = sm + 2304;

    // ---- inline Xg-slice GEMM for step tt -> smem ring slot tt%3 ----
    auto compute_xg = [&](int tt) {
        int slot = tt % 3;
        float* xb = sm + 4608 + (kh ? 6912 : 0) + slot * 2304;
        const uint32_t* axp = g_Axf + ((size_t)((tt * 4 + mi) * 32 + kh * 16) * 32 + lane) * 4;
        float xacc[4][4];
#pragma unroll
        for (int n = 0; n < 4; n++)
#pragma unroll
            for (int q = 0; q < 4; q++) xacc[n][q] = 0.f;

        uint4 fa[2], q0[2], q1[2];
        auto loadx = [&](int s, int k) {
            fa[s] = __ldcg((const uint4*)(axp + k * 128));
            q0[s] = *(const uint4*)(wxb + k * 256);
            q1[s] = *(const uint4*)(wxb + k * 256 + 4);
        };
        loadx(0, 0); loadx(1, 1);
#pragma unroll 4
        for (int kkl = 0; kkl < 16; kkl++) {
            const int cur = kkl & 1;
            uint32_t ua[4] = {fa[cur].x, fa[cur].y, fa[cur].z, fa[cur].w};
            uint4 b0 = q0[cur], b1 = q1[cur];
            if (kkl + 2 < 16) loadx(cur, kkl + 2);
            MMAF16(xacc[0], ua, b0.x, b0.y);
            MMAF16(xacc[1], ua, b0.z, b0.w);
            MMAF16(xacc[2], ua, b1.x, b1.y);
            MMAF16(xacc[3], ua, b1.z, b1.w);
        }
#pragma unroll
        for (int nt = 0; nt < 4; nt++) {
            int jc = nt * 8 + kofs;
            *(float2*)&xb[row0 * 36 + jc]       = make_float2(xacc[nt][0], xacc[nt][1]);
            *(float2*)&xb[(row0 + 8) * 36 + jc] = make_float2(xacc[nt][2], xacc[nt][3]);
        }
    };

    compute_xg(0);
    compute_xg(1);

    for (int t = 0; t < Lsz; t++) {
        if (t + 2 < Lsz) compute_xg(t + 2);
        if (t > 0) {
            // all warps poll independently (no block barrier needed here)
            while (g_step < (unsigned)t) __nanosleep(32);
        }
        const uint32_t* hs = g_hf2[(t + 1) & 1] + hroff;

        float acc[4][4];
#pragma unroll
        for (int j = 0; j < 4; j++)
#pragma unroll
            for (int q = 0; q < 4; q++) acc[j][q] = 0.f;

        uint4 fA[4];
        uint4 fB[4][2];
        auto loadA = [&](int s, int it) {
            fA[s] = __ldcg((const uint4*)(hs + (size_t)it * 512));
        };
        auto loadB = [&](int s, int it) {
            const uint32_t* bp = whb + (size_t)it * 256;
            fB[s][0] = *(const uint4*)bp;
            fB[s][1] = *(const uint4*)(bp + 4);
        };
        loadA(0, 0); loadB(0, 0);
        loadA(1, 1); loadB(1, 1);
        loadA(2, 2); loadB(2, 2);

#pragma unroll 4
        for (int it = 0; it < 32; it++) {
            const int cur = it & 3;
            uint32_t ah[4] = {fA[cur].x, fA[cur].y, fA[cur].z, fA[cur].w};
            uint4 q0 = fB[cur][0], q1 = fB[cur][1];
            if (it + 3 < 32) {
                int nx = (it + 3) & 3;
                loadA(nx, it + 3);
                loadB(nx, it + 3);
            }
            MMAF16(acc[0], ah, q0.x, q0.y);
            MMAF16(acc[1], ah, q0.z, q0.w);
            MMAF16(acc[2], ah, q1.x, q1.y);
            MMAF16(acc[3], ah, q1.z, q1.w);
        }

        {
            float* gb = (kh == 0) ? gbA : gbB;
#pragma unroll
            for (int j = 0; j < 4; j++) {
                int jc = j * 8 + kofs;
                *(float2*)&gb[row0 * 36 + jc]       = make_float2(acc[j][0], acc[j][1]);
                *(float2*)&gb[(row0 + 8) * 36 + jc] = make_float2(acc[j][2], acc[j][3]);
            }
        }
        __syncthreads();

        // fused gates / cell update; publish h quad, signal, defer outputs
        {
            int slot = t % 3;
            const float* xA = sm + 4608 + slot * 2304 + pb * 36 + cbase;
            const float* xB = xA + 6912;
            float4 xa0 = *(const float4*)xA;
            float4 xa1 = *(const float4*)(xA + 4);
            float4 xb0 = *(const float4*)xB;
            float4 xb1 = *(const float4*)(xB + 4);
            float4 a0 = *(const float4*)&gbA[pb * 36 + cbase];
            float4 a1 = *(const float4*)&gbA[pb * 36 + cbase + 4];
            float4 b0 = *(const float4*)&gbB[pb * 36 + cbase];
            float4 b1 = *(const float4*)&gbB[pb * 36 + cbase + 4];
            float mk = mask[(size_t)pb * Lsz + t];

            float p0 = xa0.x + xb0.x + a0.x + b0.x + bias0.x;
            float p1 = xa0.y + xb0.y + a0.y + b0.y + bias0.y;
            float p2 = xa0.z + xb0.z + a0.z + b0.z + bias0.z;
            float p3 = xa0.w + xb0.w + a0.w + b0.w + bias0.w;
            float f0 = 1.f / (1.f + expf(-p0));
            float i0 = 1.f / (1.f + expf(-p1));
            float o0 = 1.f / (1.f + expf(-p2));
            float u0 = tanhf(p3);
            float nc0 = f0 * cr0 + i0 * u0;
            float nh0 = o0 * tanhf(nc0);
            nh0 *= mk; nc0 *= mk;

            float q0 = xa1.x + xb1.x + a1.x + b1.x + bias1.x;
            float q1 = xa1.y + xb1.y + a1.y + b1.y + bias1.y;
            float q2 = xa1.z + xb1.z + a1.z + b1.z + bias1.z;
            float q3 = xa1.w + xb1.w + a1.w + b1.w + bias1.w;
            float f1 = 1.f / (1.f + expf(-q0));
            float i1 = 1.f / (1.f + expf(-q1));
            float o1 = 1.f / (1.f + expf(-q2));
            float u1 = tanhf(q3);
            float nc1 = f1 * cr1 + i1 * u1;
            float nh1 = o1 * tanhf(nc1);
            nh1 *= mk; nc1 *= mk;

            cr0 = nc0; cr1 = nc1;

            // publish split h first (the only cross-CTA-consumed data)
            g_hf2[t & 1][widx] = f16pair(make_float2(nh0, nh1));
            __threadfence();
            __syncthreads();
            if (tid == 0) {
                unsigned old = atomicAdd(&g_cnt, 1u);
                if (old == 128u * (unsigned)(t + 1) - 1u) g_step = (unsigned)(t + 1);
            }

            // deferred output stores (not on the critical path)
            size_t oi = ((size_t)pb * Lsz + t) * Hsz + cg * 8 + hu;
            *(float2*)(outh + oi) = make_float2(nh0, nh1);
            *(float2*)(outc + oi) = make_float2(nc0, nc1);
        }
    }
}

// ---------------------------------------------------------------------------
extern "C" void kernel_launch(void* const* d_in, const int* in_sizes, int n_in,
                              void* d_out, int out_size)
{
    const float* x    = (const float*)d_in[0];
    const float* mask = (const float*)d_in[1];
    const float* Wf   = (const float*)d_in[2];
    const float* bf   = (const float*)d_in[3];
    const float* Wi   = (const float*)d_in[4];
    const float* bi   = (const float*)d_in[5];
    const float* Wo   = (const float*)d_in[6];
    const float* bo   = (const float*)d_in[7];
    const float* Wu   = (const float*)d_in[8];
    const float* bu   = (const float*)d_in[9];
    const float* h0   = (const float*)d_in[10];
    const float* c0   = (const float*)d_in[11];

    float* outh = (float*)d_out;
    float* outc = outh + (size_t)Bsz * Lsz * Hsz;

    cudaFuncSetAttribute(lstm_fused_kernel,
                         cudaFuncAttributeMaxDynamicSharedMemorySize,
                         SMEM_FLOATS * 4);

    pack_kernel<<<8192, 256>>>(Wf, Wi, Wo, Wu, bf, bi, bo, bu, h0);
    xsplit_kernel<<<32768, 256>>>(x);
    lstm_fused_kernel<<<NCTA, 256, SMEM_FLOATS * 4>>>(mask, c0, outh, outc);
}

// round 12
// speedup vs baseline: 1.9575x; 1.1550x over previous
#include <cuda_runtime.h>
#include <cuda_fp16.h>
#include <math.h>
#include <stdint.h>

#define Bsz 64
#define Lsz 512
#define Esz 512
#define Hsz 1024
#define NG  4096     // gate-interleaved cols: col = h*4+g (0=f,1=i,2=o,3=u)
#define NCTA 128     // persistent CTAs, one 32-col group each

// smem (floats): gbA[64][36] @0, gbB @2304, xgA slots @4608+s*2304, xgB @+6912
#define SMEM_FLOATS 18432

// ---------------- device scratch ----------------
__device__ float g_ball[NG];
// Wh fp16 frags: [cg 128][kk 64][lane 32][8] (8 = 4 j-tiles x {b0,b1})
__device__ uint32_t g_Whf[(size_t)128 * 64 * 32 * 8];
// Wx fp16 frags: [cg 128][kk 32][lane 32][8]
__device__ uint32_t g_Wxf[(size_t)128 * 32 * 32 * 8];
// x fp16 frags, time-major rows m' = t*64+b: [mt 2048][kk 32][lane 32][4]
__device__ uint32_t g_Axf[(size_t)2048 * 32 * 32 * 4];
// h fp16 fragment-quads: [parity][quad 8192][4]
//   quad(kb,mi,q,klo) = ((kb*4+mi)*8+q)*4+klo ; slot r = s + 2*hi
//   covers (row = mi*16+q+8s, k2 = kb*8+klo+4hi)
__device__ uint32_t g_hf2[2][32768];
// per-K-half step counters: group g = producers of k-half g (cg in [g*64,(g+1)*64))
__device__ unsigned g_cntH[2];

// ---------------- helpers ----------------
__device__ __forceinline__ uint32_t f16pair(float2 v) {
    uint32_t r;
    asm("cvt.rn.f16x2.f32 %0, %1, %2;" : "=r"(r) : "f"(v.y), "f"(v.x));
    return r;
}
__device__ __forceinline__ float fsig(float x) {
    return __fdividef(1.f, 1.f + __expf(-x));
}
__device__ __forceinline__ float fth(float x) {
    return 2.f * __fdividef(1.f, 1.f + __expf(-2.f * x)) - 1.f;
}
#define MMAF16(d, a, b0, b1)                                                \
    asm volatile(                                                           \
        "mma.sync.aligned.m16n8k16.row.col.f32.f16.f16.f32 "                \
        "{%0,%1,%2,%3}, {%4,%5,%6,%7}, {%8,%9}, {%0,%1,%2,%3};"             \
        : "+f"((d)[0]), "+f"((d)[1]), "+f"((d)[2]), "+f"((d)[3])            \
        : "r"((a)[0]), "r"((a)[1]), "r"((a)[2]), "r"((a)[3]),               \
          "r"(b0), "r"(b1))

// ---------------------------------------------------------------------------
// Pack: Wh/Wx fp16 fragments, bias, h0 quads, counters. 8192 x 256.
// ---------------------------------------------------------------------------
__global__ void pack_kernel(const float* __restrict__ Wf, const float* __restrict__ Wi,
                            const float* __restrict__ Wo, const float* __restrict__ Wu,
                            const float* __restrict__ bf, const float* __restrict__ bi,
                            const float* __restrict__ bo, const float* __restrict__ bu,
                            const float* __restrict__ h0)
{
    int idx = blockIdx.x * 256 + threadIdx.x;   // 0 .. 2097151
    // ---- Wh fragments: idx = ((cg*64+kk)*32+lane)*8 + r3 ----
    {
        int r3   = idx & 7;
        int lane = (idx >> 3) & 31;
        int kk   = (idx >> 8) & 63;
        int cg   = idx >> 14;
        int j = r3 >> 1, half = r3 & 1;
        int col = cg * 32 + j * 8 + (lane >> 2);
        int h = col >> 2, g = col & 3;
        int k = kk * 16 + half * 8 + (lane & 3) * 2;
        const float* W = (g == 0) ? Wf : (g == 1) ? Wi : (g == 2) ? Wo : Wu;
        float w0 = W[(size_t)(Esz + k) * Hsz + h];
        float w1 = W[(size_t)(Esz + k + 1) * Hsz + h];
        g_Whf[idx] = f16pair(make_float2(w0, w1));
    }
    // ---- Wx fragments: idx = ((cg*32+kk)*32+lane)*8 + r3 ----
    if (idx < (1 << 20)) {
        int r3   = idx & 7;
        int lane = (idx >> 3) & 31;
        int kk   = (idx >> 8) & 31;
        int cg   = idx >> 13;
        int nt = r3 >> 1, b01 = r3 & 1;
        int col = cg * 32 + nt * 8 + (lane >> 2);
        int h = col >> 2, g = col & 3;
        int k = kk * 16 + (lane & 3) * 2 + b01 * 8;
        const float* W = (g == 0) ? Wf : (g == 1) ? Wi : (g == 2) ? Wo : Wu;
        float w0 = W[(size_t)k * Hsz + h];
        float w1 = W[(size_t)(k + 1) * Hsz + h];
        g_Wxf[idx] = f16pair(make_float2(w0, w1));
    }
    if (idx < NG) {
        int h = idx >> 2, g = idx & 3;
        const float* bb = (g == 0) ? bf : (g == 1) ? bi : (g == 2) ? bo : bu;
        g_ball[idx] = bb[h];
    }
    // ---- h0 quads (read by step 0 at parity 1) ----
    if (idx < 32768) {
        int r   = idx & 3;
        int klo = (idx >> 2) & 3;
        int q   = (idx >> 4) & 7;
        int mi  = (idx >> 7) & 3;
        int kb  = idx >> 9;
        int s = r & 1, hi = r >> 1;
        int b = mi * 16 + q + 8 * s;
        int k2 = kb * 8 + klo + 4 * hi;
        g_hf2[1][idx] = f16pair(make_float2(h0[(size_t)b * Hsz + 2 * k2],
                                            h0[(size_t)b * Hsz + 2 * k2 + 1]));
    }
    if (idx < 2) g_cntH[idx] = 0;
}

// ---------------------------------------------------------------------------
// x -> fp16 fragments, time-major. 32768 x 256 (idx < 2^23).
// ---------------------------------------------------------------------------
__global__ void xsplit_kernel(const float* __restrict__ x)
{
    size_t idx = (size_t)blockIdx.x * 256 + threadIdx.x;
    int r    = (int)(idx & 3);
    int lane = (int)((idx >> 2) & 31);
    int kk   = (int)((idx >> 7) & 31);
    int mt   = (int)(idx >> 12);
    int rowp = mt * 16 + (lane >> 2) + (r & 1) * 8;    // m' = t*64 + b
    int t = rowp >> 6, b = rowp & 63;
    int col = kk * 16 + (lane & 3) * 2 + (r >> 1) * 8;
    float2 v = *(const float2*)(x + ((size_t)b * Lsz + t) * Esz + col);
    g_Axf[idx] = f16pair(v);
}

// ---------------------------------------------------------------------------
// Fused persistent kernel: recurrence + inline Xg slice, fp16 single-pass.
// ---------------------------------------------------------------------------
__global__ __launch_bounds__(256, 1) void lstm_fused_kernel(
    const float* __restrict__ mask, const float* __restrict__ c0,
    float* __restrict__ outh, float* __restrict__ outc)
{
    extern __shared__ float sm[];

    const int tid = threadIdx.x;
    const int lane = tid & 31, wid = tid >> 5;
    const int mi = wid & 3, kh = wid >> 2;
    const int cg = blockIdx.x;
    const int grp = cg >> 6;                       // producer group of this CTA

    const int pb = tid >> 2;
    const int hu = (tid & 3) * 2;
    const int k2g = cg * 4 + (tid & 3);
    float cr0 = c0[(size_t)pb * Hsz + cg * 8 + hu];
    float cr1 = c0[(size_t)pb * Hsz + cg * 8 + hu + 1];

    const int row0 = mi * 16 + (lane >> 2);
    const int kofs = (lane & 3) * 2;
    const uint32_t* whb = g_Whf + ((size_t)(cg * 64 + kh * 32) * 32 + lane) * 8;
    const uint32_t* wxb = g_Wxf + ((size_t)(cg * 32 + kh * 16) * 32 + lane) * 8;
    const int cbase = (tid & 3) * 8;
    const float4 bias0 = *(const float4*)(g_ball + cg * 32 + cbase);
    const float4 bias1 = *(const float4*)(g_ball + cg * 32 + cbase + 4);

    // writer slot in fragment-quad layout
    const int kb_w = k2g >> 3, klo_w = k2g & 3, hi_w = (k2g >> 2) & 1;
    const int mi_w = pb >> 4, q_w = pb & 7, s_w = (pb >> 3) & 1;
    const size_t widx = ((size_t)((kb_w * 4 + mi_w) * 8 + q_w) * 4 + klo_w) * 4
                        + (s_w + 2 * hi_w);

    // reader base offset (uint32) at it=0: quad (kb=kh*32, mi), lane
    const size_t hroff = ((size_t)((kh * 32 * 4 + mi)) * 32 + lane) * 4;

    float* gbA = sm;
    float* gbB = sm + 2304;

    // ---- inline Xg-slice GEMM for step tt -> smem ring slot tt%3 ----
    auto compute_xg = [&](int tt) {
        int slot = tt % 3;
        float* xb = sm + 4608 + (kh ? 6912 : 0) + slot * 2304;
        const uint32_t* axp = g_Axf + ((size_t)((tt * 4 + mi) * 32 + kh * 16) * 32 + lane) * 4;
        float xacc[4][4];
#pragma unroll
        for (int n = 0; n < 4; n++)
#pragma unroll
            for (int q = 0; q < 4; q++) xacc[n][q] = 0.f;

        uint4 fa[2], q0[2], q1[2];
        auto loadx = [&](int s, int k) {
            fa[s] = __ldcg((const uint4*)(axp + k * 128));
            q0[s] = *(const uint4*)(wxb + k * 256);
            q1[s] = *(const uint4*)(wxb + k * 256 + 4);
        };
        loadx(0, 0); loadx(1, 1);
#pragma unroll 4
        for (int kkl = 0; kkl < 16; kkl++) {
            const int cur = kkl & 1;
            uint32_t ua[4] = {fa[cur].x, fa[cur].y, fa[cur].z, fa[cur].w};
            uint4 b0 = q0[cur], b1 = q1[cur];
            if (kkl + 2 < 16) loadx(cur, kkl + 2);
            MMAF16(xacc[0], ua, b0.x, b0.y);
            MMAF16(xacc[1], ua, b0.z, b0.w);
            MMAF16(xacc[2], ua, b1.x, b1.y);
            MMAF16(xacc[3], ua, b1.z, b1.w);
        }
#pragma unroll
        for (int nt = 0; nt < 4; nt++) {
            int jc = nt * 8 + kofs;
            *(float2*)&xb[row0 * 36 + jc]       = make_float2(xacc[nt][0], xacc[nt][1]);
            *(float2*)&xb[(row0 + 8) * 36 + jc] = make_float2(xacc[nt][2], xacc[nt][3]);
        }
    };

    compute_xg(0);
    compute_xg(1);

    for (int t = 0; t < Lsz; t++) {
        if (t + 2 < Lsz) compute_xg(t + 2);
        if (t > 0) {
            // each warp waits only on its producer K-half group
            unsigned tgt = 64u * (unsigned)t;
            while (((volatile unsigned*)g_cntH)[kh] < tgt) __nanosleep(32);
        }
        const uint32_t* hs = g_hf2[(t + 1) & 1] + hroff;
        float mk = __ldg(mask + (size_t)pb * Lsz + t);   // off critical path

        float acc[4][4];
#pragma unroll
        for (int j = 0; j < 4; j++)
#pragma unroll
            for (int q = 0; q < 4; q++) acc[j][q] = 0.f;

        uint4 fA[8];
        uint4 fB[2][2];
        auto loadA = [&](int s, int it) {
            fA[s] = __ldcg((const uint4*)(hs + (size_t)it * 512));
        };
        auto loadB = [&](int s, int it) {
            const uint32_t* bp = whb + (size_t)it * 256;
            fB[s][0] = *(const uint4*)bp;
            fB[s][1] = *(const uint4*)(bp + 4);
        };
#pragma unroll
        for (int i = 0; i < 8; i++) loadA(i, i);     // 8 L2 loads in flight
        loadB(0, 0); loadB(1, 1);

#pragma unroll
        for (int it = 0; it < 32; it++) {            // fully unrolled: const ring idx
            const int ca = it & 7, cb = it & 1;
            uint32_t ah[4] = {fA[ca].x, fA[ca].y, fA[ca].z, fA[ca].w};
            uint4 q0 = fB[cb][0], q1 = fB[cb][1];
            if (it + 8 < 32) loadA(ca, it + 8);
            if (it + 2 < 32) loadB(cb, it + 2);
            MMAF16(acc[0], ah, q0.x, q0.y);
            MMAF16(acc[1], ah, q0.z, q0.w);
            MMAF16(acc[2], ah, q1.x, q1.y);
            MMAF16(acc[3], ah, q1.z, q1.w);
        }

        {
            float* gb = (kh == 0) ? gbA : gbB;
#pragma unroll
            for (int j = 0; j < 4; j++) {
                int jc = j * 8 + kofs;
                *(float2*)&gb[row0 * 36 + jc]       = make_float2(acc[j][0], acc[j][1]);
                *(float2*)&gb[(row0 + 8) * 36 + jc] = make_float2(acc[j][2], acc[j][3]);
            }
        }
        __syncthreads();

        // fused gates / cell update; publish h quad, signal, defer outputs
        {
            int slot = t % 3;
            const float* xA = sm + 4608 + slot * 2304 + pb * 36 + cbase;
            const float* xB = xA + 6912;
            float4 xa0 = *(const float4*)xA;
            float4 xa1 = *(const float4*)(xA + 4);
            float4 xb0 = *(const float4*)xB;
            float4 xb1 = *(const float4*)(xB + 4);
            float4 a0 = *(const float4*)&gbA[pb * 36 + cbase];
            float4 a1 = *(const float4*)&gbA[pb * 36 + cbase + 4];
            float4 b0 = *(const float4*)&gbB[pb * 36 + cbase];
            float4 b1 = *(const float4*)&gbB[pb * 36 + cbase + 4];

            float p0 = xa0.x + xb0.x + a0.x + b0.x + bias0.x;
            float p1 = xa0.y + xb0.y + a0.y + b0.y + bias0.y;
            float p2 = xa0.z + xb0.z + a0.z + b0.z + bias0.z;
            float p3 = xa0.w + xb0.w + a0.w + b0.w + bias0.w;
            float nc0 = fsig(p0) * cr0 + fsig(p1) * fth(p3);
            float nh0 = fsig(p2) * fth(nc0);
            nh0 *= mk; nc0 *= mk;

            float q0 = xa1.x + xb1.x + a1.x + b1.x + bias1.x;
            float q1 = xa1.y + xb1.y + a1.y + b1.y + bias1.y;
            float q2 = xa1.z + xb1.z + a1.z + b1.z + bias1.z;
            float q3 = xa1.w + xb1.w + a1.w + b1.w + bias1.w;
            float nc1 = fsig(q0) * cr1 + fsig(q1) * fth(q3);
            float nh1 = fsig(q2) * fth(nc1);
            nh1 *= mk; nc1 *= mk;

            cr0 = nc0; cr1 = nc1;

            // publish split h first (the only cross-CTA-consumed data)
            g_hf2[t & 1][widx] = f16pair(make_float2(nh0, nh1));
            __threadfence();
            __syncthreads();
            if (tid == 0) atomicAdd(&g_cntH[grp], 1u);   // no-return -> RED

            // deferred output stores (not on the critical path)
            size_t oi = ((size_t)pb * Lsz + t) * Hsz + cg * 8 + hu;
            *(float2*)(outh + oi) = make_float2(nh0, nh1);
            *(float2*)(outc + oi) = make_float2(nc0, nc1);
        }
    }
}

// ---------------------------------------------------------------------------
extern "C" void kernel_launch(void* const* d_in, const int* in_sizes, int n_in,
                              void* d_out, int out_size)
{
    const float* x    = (const float*)d_in[0];
    const float* mask = (const float*)d_in[1];
    const float* Wf   = (const float*)d_in[2];
    const float* bf   = (const float*)d_in[3];
    const float* Wi   = (const float*)d_in[4];
    const float* bi   = (const float*)d_in[5];
    const float* Wo   = (const float*)d_in[6];
    const float* bo   = (const float*)d_in[7];
    const float* Wu   = (const float*)d_in[8];
    const float* bu   = (const float*)d_in[9];
    const float* h0   = (const float*)d_in[10];
    const float* c0   = (const float*)d_in[11];

    float* outh = (float*)d_out;
    float* outc = outh + (size_t)Bsz * Lsz * Hsz;

    cudaFuncSetAttribute(lstm_fused_kernel,
                         cudaFuncAttributeMaxDynamicSharedMemorySize,
                         SMEM_FLOATS * 4);

    pack_kernel<<<8192, 256>>>(Wf, Wi, Wo, Wu, bf, bi, bo, bu, h0);
    xsplit_kernel<<<32768, 256>>>(x);
    lstm_fused_kernel<<<NCTA, 256, SMEM_FLOATS * 4>>>(mask, c0, outh, outc);
}

// round 13
// speedup vs baseline: 1.9874x; 1.0152x over previous
#include <cuda_runtime.h>
#include <cuda_fp16.h>
#include <math.h>
#include <stdint.h>

#define Bsz 64
#define Lsz 512
#define Esz 512
#define Hsz 1024
#define NG  4096     // gate-interleaved cols: col = h*4+g (0=f,1=i,2=o,3=u)
#define NCTA 128     // persistent CTAs, one 32-col group each

// smem (floats): gbA[64][36] @0, gbB @2304, xgA slots @4608+s*2304, xgB @+6912
#define SMEM_FLOATS 18432

// ---------------- device scratch ----------------
__device__ float g_ball[NG];
// Wh fp16 frags: [cg 128][kk 64][lane 32][8] (8 = 4 j-tiles x {b0,b1})
__device__ uint32_t g_Whf[(size_t)128 * 64 * 32 * 8];
// Wx fp16 frags: [cg 128][kk 32][lane 32][8]
__device__ uint32_t g_Wxf[(size_t)128 * 32 * 32 * 8];
// x fp16 frags, time-major rows m' = t*64+b: [mt 2048][kk 32][lane 32][4]
__device__ uint32_t g_Axf[(size_t)2048 * 32 * 32 * 4];
// h fp16 fragment-quads: [parity][quad 8192][4]
//   quad(kb,mi,q,klo) = ((kb*4+mi)*8+q)*4+klo ; slot r = s + 2*hi
//   covers (row = mi*16+q+8s, k2 = kb*8+klo+4hi)
__device__ uint32_t g_hf2[2][32768];
// fine-grained step counters: group g = CTAs [16g, 16g+16) (produce k2 [64g,64g+64))
__device__ unsigned g_cntG[8];

// ---------------- helpers ----------------
__device__ __forceinline__ uint32_t f16pair(float2 v) {
    uint32_t r;
    asm("cvt.rn.f16x2.f32 %0, %1, %2;" : "=r"(r) : "f"(v.y), "f"(v.x));
    return r;
}
__device__ __forceinline__ float fsig(float x) {
    return __fdividef(1.f, 1.f + __expf(-x));
}
__device__ __forceinline__ float fth(float x) {
    return 2.f * __fdividef(1.f, 1.f + __expf(-2.f * x)) - 1.f;
}
#define MMAF16(d, a, b0, b1)                                                \
    asm volatile(                                                           \
        "mma.sync.aligned.m16n8k16.row.col.f32.f16.f16.f32 "                \
        "{%0,%1,%2,%3}, {%4,%5,%6,%7}, {%8,%9}, {%0,%1,%2,%3};"             \
        : "+f"((d)[0]), "+f"((d)[1]), "+f"((d)[2]), "+f"((d)[3])            \
        : "r"((a)[0]), "r"((a)[1]), "r"((a)[2]), "r"((a)[3]),               \
          "r"(b0), "r"(b1))

// ---------------------------------------------------------------------------
// Pack: Wh/Wx fp16 fragments, bias, h0 quads, counters. 8192 x 256.
// ---------------------------------------------------------------------------
__global__ void pack_kernel(const float* __restrict__ Wf, const float* __restrict__ Wi,
                            const float* __restrict__ Wo, const float* __restrict__ Wu,
                            const float* __restrict__ bf, const float* __restrict__ bi,
                            const float* __restrict__ bo, const float* __restrict__ bu,
                            const float* __restrict__ h0)
{
    int idx = blockIdx.x * 256 + threadIdx.x;   // 0 .. 2097151
    // ---- Wh fragments: idx = ((cg*64+kk)*32+lane)*8 + r3 ----
    {
        int r3   = idx & 7;
        int lane = (idx >> 3) & 31;
        int kk   = (idx >> 8) & 63;
        int cg   = idx >> 14;
        int j = r3 >> 1, half = r3 & 1;
        int col = cg * 32 + j * 8 + (lane >> 2);
        int h = col >> 2, g = col & 3;
        int k = kk * 16 + half * 8 + (lane & 3) * 2;
        const float* W = (g == 0) ? Wf : (g == 1) ? Wi : (g == 2) ? Wo : Wu;
        float w0 = W[(size_t)(Esz + k) * Hsz + h];
        float w1 = W[(size_t)(Esz + k + 1) * Hsz + h];
        g_Whf[idx] = f16pair(make_float2(w0, w1));
    }
    // ---- Wx fragments: idx = ((cg*32+kk)*32+lane)*8 + r3 ----
    if (idx < (1 << 20)) {
        int r3   = idx & 7;
        int lane = (idx >> 3) & 31;
        int kk   = (idx >> 8) & 31;
        int cg   = idx >> 13;
        int nt = r3 >> 1, b01 = r3 & 1;
        int col = cg * 32 + nt * 8 + (lane >> 2);
        int h = col >> 2, g = col & 3;
        int k = kk * 16 + (lane & 3) * 2 + b01 * 8;
        const float* W = (g == 0) ? Wf : (g == 1) ? Wi : (g == 2) ? Wo : Wu;
        float w0 = W[(size_t)k * Hsz + h];
        float w1 = W[(size_t)(k + 1) * Hsz + h];
        g_Wxf[idx] = f16pair(make_float2(w0, w1));
    }
    if (idx < NG) {
        int h = idx >> 2, g = idx & 3;
        const float* bb = (g == 0) ? bf : (g == 1) ? bi : (g == 2) ? bo : bu;
        g_ball[idx] = bb[h];
    }
    // ---- h0 quads (read by step 0 at parity 1) ----
    if (idx < 32768) {
        int r   = idx & 3;
        int klo = (idx >> 2) & 3;
        int q   = (idx >> 4) & 7;
        int mi  = (idx >> 7) & 3;
        int kb  = idx >> 9;
        int s = r & 1, hi = r >> 1;
        int b = mi * 16 + q + 8 * s;
        int k2 = kb * 8 + klo + 4 * hi;
        g_hf2[1][idx] = f16pair(make_float2(h0[(size_t)b * Hsz + 2 * k2],
                                            h0[(size_t)b * Hsz + 2 * k2 + 1]));
    }
    if (idx < 8) g_cntG[idx] = 0;
}

// ---------------------------------------------------------------------------
// x -> fp16 fragments, time-major. 32768 x 256 (idx < 2^23).
// ---------------------------------------------------------------------------
__global__ void xsplit_kernel(const float* __restrict__ x)
{
    size_t idx = (size_t)blockIdx.x * 256 + threadIdx.x;
    int r    = (int)(idx & 3);
    int lane = (int)((idx >> 2) & 31);
    int kk   = (int)((idx >> 7) & 31);
    int mt   = (int)(idx >> 12);
    int rowp = mt * 16 + (lane >> 2) + (r & 1) * 8;    // m' = t*64 + b
    int t = rowp >> 6, b = rowp & 63;
    int col = kk * 16 + (lane & 3) * 2 + (r >> 1) * 8;
    float2 v = *(const float2*)(x + ((size_t)b * Lsz + t) * Esz + col);
    g_Axf[idx] = f16pair(v);
}

// ---------------------------------------------------------------------------
// Fused persistent kernel: recurrence + inline Xg slice, fp16 single-pass,
// fine-grained producer groups (8 x 16 CTAs), staged A consumption.
// ---------------------------------------------------------------------------
__global__ __launch_bounds__(256, 1) void lstm_fused_kernel(
    const float* __restrict__ mask, const float* __restrict__ c0,
    float* __restrict__ outh, float* __restrict__ outc)
{
    extern __shared__ float sm[];

    const int tid = threadIdx.x;
    const int lane = tid & 31, wid = tid >> 5;
    const int mi = wid & 3, kh = wid >> 2;
    const int cg = blockIdx.x;
    const int grp = cg >> 4;                       // this CTA's producer group

    const int pb = tid >> 2;
    const int hu = (tid & 3) * 2;
    const int k2g = cg * 4 + (tid & 3);
    float cr0 = c0[(size_t)pb * Hsz + cg * 8 + hu];
    float cr1 = c0[(size_t)pb * Hsz + cg * 8 + hu + 1];

    const int row0 = mi * 16 + (lane >> 2);
    const int kofs = (lane & 3) * 2;
    const uint32_t* whb = g_Whf + ((size_t)(cg * 64 + kh * 32) * 32 + lane) * 8;
    const uint32_t* wxb = g_Wxf + ((size_t)(cg * 32 + kh * 16) * 32 + lane) * 8;
    const int cbase = (tid & 3) * 8;
    const float4 bias0 = *(const float4*)(g_ball + cg * 32 + cbase);
    const float4 bias1 = *(const float4*)(g_ball + cg * 32 + cbase + 4);

    // writer slot in fragment-quad layout
    const int kb_w = k2g >> 3, klo_w = k2g & 3, hi_w = (k2g >> 2) & 1;
    const int mi_w = pb >> 4, q_w = pb & 7, s_w = (pb >> 3) & 1;
    const size_t widx = ((size_t)((kb_w * 4 + mi_w) * 8 + q_w) * 4 + klo_w) * 4
                        + (s_w + 2 * hi_w);

    // reader base offset (uint32) at it=0: quad (kb=kh*32, mi), lane
    const size_t hroff = ((size_t)((kh * 32 * 4 + mi)) * 32 + lane) * 4;

    float* gbA = sm;
    float* gbB = sm + 2304;

    // ---- inline Xg-slice GEMM for step tt -> smem ring slot tt%3 ----
    auto compute_xg = [&](int tt) {
        int slot = tt % 3;
        float* xb = sm + 4608 + (kh ? 6912 : 0) + slot * 2304;
        const uint32_t* axp = g_Axf + ((size_t)((tt * 4 + mi) * 32 + kh * 16) * 32 + lane) * 4;
        float xacc[4][4];
#pragma unroll
        for (int n = 0; n < 4; n++)
#pragma unroll
            for (int q = 0; q < 4; q++) xacc[n][q] = 0.f;

        uint4 fa[2], q0[2], q1[2];
        auto loadx = [&](int s, int k) {
            fa[s] = __ldcg((const uint4*)(axp + k * 128));
            q0[s] = *(const uint4*)(wxb + k * 256);
            q1[s] = *(const uint4*)(wxb + k * 256 + 4);
        };
        loadx(0, 0); loadx(1, 1);
#pragma unroll 4
        for (int kkl = 0; kkl < 16; kkl++) {
            const int cur = kkl & 1;
            uint32_t ua[4] = {fa[cur].x, fa[cur].y, fa[cur].z, fa[cur].w};
            uint4 b0 = q0[cur], b1 = q1[cur];
            if (kkl + 2 < 16) loadx(cur, kkl + 2);
            MMAF16(xacc[0], ua, b0.x, b0.y);
            MMAF16(xacc[1], ua, b0.z, b0.w);
            MMAF16(xacc[2], ua, b1.x, b1.y);
            MMAF16(xacc[3], ua, b1.z, b1.w);
        }
#pragma unroll
        for (int nt = 0; nt < 4; nt++) {
            int jc = nt * 8 + kofs;
            *(float2*)&xb[row0 * 36 + jc]       = make_float2(xacc[nt][0], xacc[nt][1]);
            *(float2*)&xb[(row0 + 8) * 36 + jc] = make_float2(xacc[nt][2], xacc[nt][3]);
        }
    };

    compute_xg(0);
    compute_xg(1);

    for (int t = 0; t < Lsz; t++) {
        if (t + 2 < Lsz) compute_xg(t + 2);
        const unsigned tgt = 16u * (unsigned)t;
        const uint32_t* hs = g_hf2[(t + 1) & 1] + hroff;
        float mk = __ldg(mask + (size_t)pb * Lsz + t);   // off critical path

        float acc[4][4];
#pragma unroll
        for (int j = 0; j < 4; j++)
#pragma unroll
            for (int q = 0; q < 4; q++) acc[j][q] = 0.f;

        uint4 fA[16];
        uint4 fB[2][2];
        auto loadB = [&](int s, int it) {
            const uint32_t* bp = whb + (size_t)it * 256;
            fB[s][0] = *(const uint4*)bp;
            fB[s][1] = *(const uint4*)(bp + 4);
        };

        // stage 0: wait its 16 producers, launch its 8 A-quads
        while (((volatile unsigned*)g_cntG)[4 * kh] < tgt) __nanosleep(32);
#pragma unroll
        for (int i = 0; i < 8; i++)
            fA[i] = __ldcg((const uint4*)(hs + (size_t)i * 512));
        loadB(0, 0); loadB(1, 1);

#pragma unroll
        for (int gi = 0; gi < 4; gi++) {
            if (gi < 3) {
                // next group's producers (usually already done), then its loads
                while (((volatile unsigned*)g_cntG)[4 * kh + gi + 1] < tgt) __nanosleep(32);
#pragma unroll
                for (int i = 0; i < 8; i++) {
                    int it2 = (gi + 1) * 8 + i;
                    fA[it2 & 15] = __ldcg((const uint4*)(hs + (size_t)it2 * 512));
                }
            }
#pragma unroll
            for (int i = 0; i < 8; i++) {
                const int it = gi * 8 + i;
                const int ca = it & 15, cb = it & 1;
                uint32_t ah[4] = {fA[ca].x, fA[ca].y, fA[ca].z, fA[ca].w};
                uint4 q0 = fB[cb][0], q1 = fB[cb][1];
                if (it + 2 < 32) loadB(cb, it + 2);
                MMAF16(acc[0], ah, q0.x, q0.y);
                MMAF16(acc[1], ah, q0.z, q0.w);
                MMAF16(acc[2], ah, q1.x, q1.y);
                MMAF16(acc[3], ah, q1.z, q1.w);
            }
        }

        {
            float* gb = (kh == 0) ? gbA : gbB;
#pragma unroll
            for (int j = 0; j < 4; j++) {
                int jc = j * 8 + kofs;
                *(float2*)&gb[row0 * 36 + jc]       = make_float2(acc[j][0], acc[j][1]);
                *(float2*)&gb[(row0 + 8) * 36 + jc] = make_float2(acc[j][2], acc[j][3]);
            }
        }
        __syncthreads();

        // fused gates / cell update; publish h quad, signal, defer outputs
        {
            int slot = t % 3;
            const float* xA = sm + 4608 + slot * 2304 + pb * 36 + cbase;
            const float* xB = xA + 6912;
            float4 xa0 = *(const float4*)xA;
            float4 xa1 = *(const float4*)(xA + 4);
            float4 xb0 = *(const float4*)xB;
            float4 xb1 = *(const float4*)(xB + 4);
            float4 a0 = *(const float4*)&gbA[pb * 36 + cbase];
            float4 a1 = *(const float4*)&gbA[pb * 36 + cbase + 4];
            float4 b0 = *(const float4*)&gbB[pb * 36 + cbase];
            float4 b1 = *(const float4*)&gbB[pb * 36 + cbase + 4];

            float p0 = xa0.x + xb0.x + a0.x + b0.x + bias0.x;
            float p1 = xa0.y + xb0.y + a0.y + b0.y + bias0.y;
            float p2 = xa0.z + xb0.z + a0.z + b0.z + bias0.z;
            float p3 = xa0.w + xb0.w + a0.w + b0.w + bias0.w;
            float nc0 = fsig(p0) * cr0 + fsig(p1) * fth(p3);
            float nh0 = fsig(p2) * fth(nc0);
            nh0 *= mk; nc0 *= mk;

            float q0 = xa1.x + xb1.x + a1.x + b1.x + bias1.x;
            float q1 = xa1.y + xb1.y + a1.y + b1.y + bias1.y;
            float q2 = xa1.z + xb1.z + a1.z + b1.z + bias1.z;
            float q3 = xa1.w + xb1.w + a1.w + b1.w + bias1.w;
            float nc1 = fsig(q0) * cr1 + fsig(q1) * fth(q3);
            float nh1 = fsig(q2) * fth(nc1);
            nh1 *= mk; nc1 *= mk;

            cr0 = nc0; cr1 = nc1;

            // publish split h (the only cross-CTA-consumed data)
            g_hf2[t & 1][widx] = f16pair(make_float2(nh0, nh1));
            __syncthreads();                      // CTA-scope release of all publishes
            if (tid == 0) {
                __threadfence();                  // cumulative: releases whole CTA's writes
                atomicAdd(&g_cntG[grp], 1u);      // no-return -> RED
            }

            // deferred output stores (not on the critical path)
            size_t oi = ((size_t)pb * Lsz + t) * Hsz + cg * 8 + hu;
            *(float2*)(outh + oi) = make_float2(nh0, nh1);
            *(float2*)(outc + oi) = make_float2(nc0, nc1);
        }
    }
}

// ---------------------------------------------------------------------------
extern "C" void kernel_launch(void* const* d_in, const int* in_sizes, int n_in,
                              void* d_out, int out_size)
{
    const float* x    = (const float*)d_in[0];
    const float* mask = (const float*)d_in[1];
    const float* Wf   = (const float*)d_in[2];
    const float* bf   = (const float*)d_in[3];
    const float* Wi   = (const float*)d_in[4];
    const float* bi   = (const float*)d_in[5];
    const float* Wo   = (const float*)d_in[6];
    const float* bo   = (const float*)d_in[7];
    const float* Wu   = (const float*)d_in[8];
    const float* bu   = (const float*)d_in[9];
    const float* h0   = (const float*)d_in[10];
    const float* c0   = (const float*)d_in[11];

    float* outh = (float*)d_out;
    float* outc = outh + (size_t)Bsz * Lsz * Hsz;

    cudaFuncSetAttribute(lstm_fused_kernel,
                         cudaFuncAttributeMaxDynamicSharedMemorySize,
                         SMEM_FLOATS * 4);

    pack_kernel<<<8192, 256>>>(Wf, Wi, Wo, Wu, bf, bi, bo, bu, h0);
    xsplit_kernel<<<32768, 256>>>(x);
    lstm_fused_kernel<<<NCTA, 256, SMEM_FLOATS * 4>>>(mask, c0, outh, outc);
}